// round 1
// baseline (speedup 1.0000x reference)
#include <cuda_runtime.h>
#include <math.h>

#define T_TOK   2048
#define DIM     1024
#define NEXP    8
#define HID     4096
#define TOPK    2
#define MAXROWS (T_TOK * TOPK)   // 4096

// ---------------- scratch (__device__ globals: no allocation allowed) --------
__device__ float g_H[(size_t)MAXROWS * HID];   // 64 MB hidden activations
__device__ int   g_rowmap[MAXROWS];            // slot -> token
__device__ float g_rowgate[MAXROWS];           // slot -> gate weight
__device__ int   g_counts[NEXP];
__device__ int   g_cursor[NEXP];
__device__ int   g_offsets[NEXP + 1];
__device__ int   g_tok_e[T_TOK * TOPK];
__device__ float g_tok_w[T_TOK * TOPK];
__device__ float g_dummy[1];

// ---------------- K0: zero output + counters --------------------------------
__global__ void k_zero(float* __restrict__ out)
{
    size_t i = ((size_t)blockIdx.x * blockDim.x + threadIdx.x) * 4;
    if (i < (size_t)T_TOK * DIM) {
        float4 z = make_float4(0.f, 0.f, 0.f, 0.f);
        *(float4*)(out + i) = z;
    }
    if (blockIdx.x == 0 && threadIdx.x < NEXP) {
        g_counts[threadIdx.x] = 0;
        g_cursor[threadIdx.x] = 0;
    }
}

// ---------------- K1: router (scores, softmax, top-2, counts) ----------------
__global__ void k_router(const float* __restrict__ u,
                         const float* __restrict__ cent,
                         const float* __restrict__ bias)
{
    int t    = blockIdx.x;
    int warp = threadIdx.x >> 5;
    int lane = threadIdx.x & 31;

    const float* ur = u + (size_t)t * DIM;
    const float* cr = cent + (size_t)warp * DIM;

    float s = 0.f;
    #pragma unroll 8
    for (int i = lane; i < DIM; i += 32) s += ur[i] * cr[i];
    #pragma unroll
    for (int o = 16; o; o >>= 1) s += __shfl_xor_sync(0xffffffffu, s, o);

    __shared__ float sc[NEXP];
    if (lane == 0) sc[warp] = s + bias[warp];
    __syncthreads();

    if (threadIdx.x == 0) {
        float m = sc[0];
        #pragma unroll
        for (int e = 1; e < NEXP; e++) m = fmaxf(m, sc[e]);
        float p[NEXP];
        float den = 0.f;
        #pragma unroll
        for (int e = 0; e < NEXP; e++) { p[e] = __expf(sc[e] - m); den += p[e]; }

        int e0 = 0;
        #pragma unroll
        for (int e = 1; e < NEXP; e++) if (p[e] > p[e0]) e0 = e;
        int e1 = (e0 == 0) ? 1 : 0;
        #pragma unroll
        for (int e = 0; e < NEXP; e++) if (e != e0 && p[e] > p[e1]) e1 = e;

        float inv = 1.f / den;
        g_tok_e[t * 2 + 0] = e0;  g_tok_w[t * 2 + 0] = p[e0] * inv;
        g_tok_e[t * 2 + 1] = e1;  g_tok_w[t * 2 + 1] = p[e1] * inv;
        atomicAdd(&g_counts[e0], 1);
        atomicAdd(&g_counts[e1], 1);
    }
}

// ---------------- K2: prefix-sum offsets + maxvio ----------------------------
__global__ void k_offsets(float* __restrict__ maxvio_out)
{
    if (threadIdx.x == 0) {
        int off = 0, mx = 0;
        #pragma unroll
        for (int e = 0; e < NEXP; e++) {
            g_offsets[e] = off;
            int c = g_counts[e];
            off += c;
            if (c > mx) mx = c;
        }
        g_offsets[NEXP] = off;
        const float perfect = (float)(TOPK * T_TOK) / (float)NEXP; // 512
        *maxvio_out = ((float)mx - perfect) / perfect;
    }
}

// ---------------- K3: scatter token rows into per-expert segments ------------
__global__ void k_scatter()
{
    int t = blockIdx.x * blockDim.x + threadIdx.x;
    if (t >= T_TOK) return;
    #pragma unroll
    for (int k = 0; k < TOPK; k++) {
        int e = g_tok_e[t * 2 + k];
        int slot = g_offsets[e] + atomicAdd(&g_cursor[e], 1);
        g_rowmap[slot]  = t;
        g_rowgate[slot] = g_tok_w[t * 2 + k];
    }
}

// ---------------- GEMM1: H = relu(X @ W1[e] + b1[e]) -------------------------
// Tiles 64x64, BK=16, 256 threads, 4x4 per thread.
__global__ __launch_bounds__(256) void k_gemm1(const float* __restrict__ u,
                                               const float* __restrict__ W1,
                                               const float* __restrict__ b1)
{
    int e    = blockIdx.z;
    int base = g_offsets[e];
    int cnt  = g_offsets[e + 1] - base;
    int m0   = blockIdx.y * 64;
    if (m0 >= cnt) return;
    int n0   = blockIdx.x * 64;

    const float* B = W1 + (size_t)e * DIM * HID;

    __shared__ float As[16][64];
    __shared__ float Bs[16][64];

    int tid = threadIdx.x;
    int tx  = tid & 15;
    int ty  = tid >> 4;

    float acc[4][4] = {};

    // A-load mapping: each thread loads one float4 from one row
    int mA = tid >> 2;          // 0..63 row within tile
    int kA = (tid & 3) * 4;     // 0..12 k offset
    const float* Arow = nullptr;
    {
        int r = m0 + mA;
        if (r < cnt) Arow = u + (size_t)g_rowmap[base + r] * DIM;
    }
    // B-load mapping: each thread loads one float4
    int kB = tid >> 4;          // 0..15
    int nB = (tid & 15) * 4;    // 0..60

    for (int k0 = 0; k0 < DIM; k0 += 16) {
        float4 av = Arow ? *(const float4*)(Arow + k0 + kA)
                         : make_float4(0.f, 0.f, 0.f, 0.f);
        As[kA + 0][mA] = av.x;
        As[kA + 1][mA] = av.y;
        As[kA + 2][mA] = av.z;
        As[kA + 3][mA] = av.w;
        *(float4*)&Bs[kB][nB] =
            *(const float4*)(B + (size_t)(k0 + kB) * HID + n0 + nB);
        __syncthreads();

        #pragma unroll
        for (int kk = 0; kk < 16; kk++) {
            float a[4], b[4];
            #pragma unroll
            for (int i = 0; i < 4; i++) a[i] = As[kk][ty * 4 + i];
            #pragma unroll
            for (int j = 0; j < 4; j++) b[j] = Bs[kk][tx * 4 + j];
            #pragma unroll
            for (int i = 0; i < 4; i++)
                #pragma unroll
                for (int j = 0; j < 4; j++)
                    acc[i][j] = fmaf(a[i], b[j], acc[i][j]);
        }
        __syncthreads();
    }

    #pragma unroll
    for (int i = 0; i < 4; i++) {
        int r = m0 + ty * 4 + i;
        if (r < cnt) {
            float* Hrow = g_H + (size_t)(base + r) * HID + n0;
            #pragma unroll
            for (int j = 0; j < 4; j++) {
                int n = tx * 4 + j;
                float v = acc[i][j] + b1[(size_t)e * HID + n0 + n];
                Hrow[n] = fmaxf(v, 0.f);
            }
        }
    }
}

// ---------------- GEMM2: out[tok] += w * (H @ W2[e] + b2[e]) -----------------
__global__ __launch_bounds__(256) void k_gemm2(const float* __restrict__ W2,
                                               const float* __restrict__ b2,
                                               float* __restrict__ out)
{
    int e    = blockIdx.z;
    int base = g_offsets[e];
    int cnt  = g_offsets[e + 1] - base;
    int m0   = blockIdx.y * 64;
    if (m0 >= cnt) return;
    int n0   = blockIdx.x * 64;

    const float* B = W2 + (size_t)e * HID * DIM;

    __shared__ float As[16][64];
    __shared__ float Bs[16][64];

    int tid = threadIdx.x;
    int tx  = tid & 15;
    int ty  = tid >> 4;

    float acc[4][4] = {};

    int mA = tid >> 2;
    int kA = (tid & 3) * 4;
    const float* Arow = nullptr;
    {
        int r = m0 + mA;
        if (r < cnt) Arow = g_H + (size_t)(base + r) * HID;
    }
    int kB = tid >> 4;
    int nB = (tid & 15) * 4;

    for (int k0 = 0; k0 < HID; k0 += 16) {
        float4 av = Arow ? *(const float4*)(Arow + k0 + kA)
                         : make_float4(0.f, 0.f, 0.f, 0.f);
        As[kA + 0][mA] = av.x;
        As[kA + 1][mA] = av.y;
        As[kA + 2][mA] = av.z;
        As[kA + 3][mA] = av.w;
        *(float4*)&Bs[kB][nB] =
            *(const float4*)(B + (size_t)(k0 + kB) * DIM + n0 + nB);
        __syncthreads();

        #pragma unroll
        for (int kk = 0; kk < 16; kk++) {
            float a[4], b[4];
            #pragma unroll
            for (int i = 0; i < 4; i++) a[i] = As[kk][ty * 4 + i];
            #pragma unroll
            for (int j = 0; j < 4; j++) b[j] = Bs[kk][tx * 4 + j];
            #pragma unroll
            for (int i = 0; i < 4; i++)
                #pragma unroll
                for (int j = 0; j < 4; j++)
                    acc[i][j] = fmaf(a[i], b[j], acc[i][j]);
        }
        __syncthreads();
    }

    #pragma unroll
    for (int i = 0; i < 4; i++) {
        int r = m0 + ty * 4 + i;
        if (r < cnt) {
            int   tok = g_rowmap[base + r];
            float w   = g_rowgate[base + r];
            float* orow = out + (size_t)tok * DIM + n0;
            #pragma unroll
            for (int j = 0; j < 4; j++) {
                int n = tx * 4 + j;
                float v = acc[i][j] + b2[(size_t)e * DIM + n0 + n];
                atomicAdd(&orow[n], w * v);
            }
        }
    }
}

// ---------------- launch -----------------------------------------------------
extern "C" void kernel_launch(void* const* d_in, const int* in_sizes, int n_in,
                              void* d_out, int out_size)
{
    const float* u    = (const float*)d_in[0];   // [2,1024,1024]
    const float* cent = (const float*)d_in[1];   // [8,1024]
    const float* bias = (const float*)d_in[2];   // [8]
    const float* W1   = (const float*)d_in[3];   // [8,1024,4096]
    const float* b1   = (const float*)d_in[4];   // [8,4096]
    const float* W2   = (const float*)d_in[5];   // [8,4096,1024]
    const float* b2   = (const float*)d_in[6];   // [8,1024]
    float* out = (float*)d_out;

    // maxvio destination: appended after the [T, DIM] tensor if present
    float* maxvio_ptr;
    if (out_size > T_TOK * DIM) {
        maxvio_ptr = out + (size_t)T_TOK * DIM;
    } else {
        cudaGetSymbolAddress((void**)&maxvio_ptr, g_dummy);
    }

    k_zero<<<(T_TOK * DIM / 4 + 255) / 256, 256>>>(out);
    k_router<<<T_TOK, 256>>>(u, cent, bias);
    k_offsets<<<1, 32>>>(maxvio_ptr);
    k_scatter<<<(T_TOK + 255) / 256, 256>>>();
    k_gemm1<<<dim3(HID / 64, MAXROWS / 64, NEXP), 256>>>(u, W1, b1);
    k_gemm2<<<dim3(DIM / 64, MAXROWS / 64, NEXP), 256>>>(W2, b2, out);
}

// round 3
// speedup vs baseline: 3.6871x; 3.6871x over previous
#include <cuda_runtime.h>
#include <cstdint>
#include <math.h>

#define T_TOK   2048
#define DIM     1024
#define NEXP    8
#define HID     4096
#define TOPK    2
#define MAXROWS (T_TOK * TOPK)   // 4096

// ---------------- scratch (__device__ globals) -------------------------------
__device__ float g_H[(size_t)MAXROWS * HID];   // 64 MB hidden activations
__device__ int   g_rowmap[MAXROWS];
__device__ float g_rowgate[MAXROWS];
__device__ int   g_counts[NEXP];
__device__ int   g_cursor[NEXP];
__device__ int   g_offsets[NEXP + 1];
__device__ int   g_tok_e[T_TOK * TOPK];
__device__ float g_tok_w[T_TOK * TOPK];
__device__ float g_dummy[1];

// ---------------- helpers ----------------------------------------------------
__device__ __forceinline__ uint32_t smem_u32(const void* p) {
    uint32_t a;
    asm("{ .reg .u64 t; cvta.to.shared.u64 t, %1; cvt.u32.u64 %0, t; }"
        : "=r"(a) : "l"(p));
    return a;
}
__device__ __forceinline__ uint32_t tf32u(float x) {
    float r;
    asm("cvt.rna.tf32.f32 %0, %1;" : "=f"(r) : "f"(x));
    return __float_as_uint(r);
}

#define CP16(dst, src) \
    asm volatile("cp.async.cg.shared.global [%0], [%1], 16;" :: "r"(dst), "l"(src))
#define CP_COMMIT()  asm volatile("cp.async.commit_group;" ::: "memory")
#define CP_WAIT1()   asm volatile("cp.async.wait_group 1;" ::: "memory")
#define CP_WAITALL() asm volatile("cp.async.wait_all;" ::: "memory")

#define MMA_TF32(d, a, b) \
    asm volatile("mma.sync.aligned.m16n8k8.row.col.f32.tf32.tf32.f32 " \
        "{%0,%1,%2,%3}, {%4,%5,%6,%7}, {%8,%9}, {%0,%1,%2,%3};" \
        : "+f"((d)[0]), "+f"((d)[1]), "+f"((d)[2]), "+f"((d)[3]) \
        : "r"((a)[0]), "r"((a)[1]), "r"((a)[2]), "r"((a)[3]), \
          "r"((b)[0]), "r"((b)[1]))

// ---------------- small kernels ----------------------------------------------
__global__ void k_zero(float* __restrict__ out)
{
    size_t i = ((size_t)blockIdx.x * blockDim.x + threadIdx.x) * 4;
    if (i < (size_t)T_TOK * DIM) {
        *(float4*)(out + i) = make_float4(0.f, 0.f, 0.f, 0.f);
    }
    if (blockIdx.x == 0 && threadIdx.x < NEXP) {
        g_counts[threadIdx.x] = 0;
        g_cursor[threadIdx.x] = 0;
    }
}

__global__ void k_router(const float* __restrict__ u,
                         const float* __restrict__ cent,
                         const float* __restrict__ bias)
{
    int t    = blockIdx.x;
    int warp = threadIdx.x >> 5;
    int lane = threadIdx.x & 31;

    const float* ur = u + (size_t)t * DIM;
    const float* cr = cent + (size_t)warp * DIM;

    float s = 0.f;
    #pragma unroll 8
    for (int i = lane; i < DIM; i += 32) s += ur[i] * cr[i];
    #pragma unroll
    for (int o = 16; o; o >>= 1) s += __shfl_xor_sync(0xffffffffu, s, o);

    __shared__ float sc[NEXP];
    if (lane == 0) sc[warp] = s + bias[warp];
    __syncthreads();

    if (threadIdx.x == 0) {
        float m = sc[0];
        #pragma unroll
        for (int e = 1; e < NEXP; e++) m = fmaxf(m, sc[e]);
        float p[NEXP];
        float den = 0.f;
        #pragma unroll
        for (int e = 0; e < NEXP; e++) { p[e] = __expf(sc[e] - m); den += p[e]; }

        int e0 = 0;
        #pragma unroll
        for (int e = 1; e < NEXP; e++) if (p[e] > p[e0]) e0 = e;
        int e1 = (e0 == 0) ? 1 : 0;
        #pragma unroll
        for (int e = 0; e < NEXP; e++) if (e != e0 && p[e] > p[e1]) e1 = e;

        float inv = 1.f / den;
        g_tok_e[t * 2 + 0] = e0;  g_tok_w[t * 2 + 0] = p[e0] * inv;
        g_tok_e[t * 2 + 1] = e1;  g_tok_w[t * 2 + 1] = p[e1] * inv;
        atomicAdd(&g_counts[e0], 1);
        atomicAdd(&g_counts[e1], 1);
    }
}

__global__ void k_offsets(float* __restrict__ maxvio_out)
{
    if (threadIdx.x == 0) {
        int off = 0, mx = 0;
        #pragma unroll
        for (int e = 0; e < NEXP; e++) {
            g_offsets[e] = off;
            int c = g_counts[e];
            off += c;
            if (c > mx) mx = c;
        }
        g_offsets[NEXP] = off;
        const float perfect = (float)(TOPK * T_TOK) / (float)NEXP;
        *maxvio_out = ((float)mx - perfect) / perfect;
    }
}

__global__ void k_scatter()
{
    int t = blockIdx.x * blockDim.x + threadIdx.x;
    if (t >= T_TOK) return;
    #pragma unroll
    for (int k = 0; k < TOPK; k++) {
        int e = g_tok_e[t * 2 + k];
        int slot = g_offsets[e] + atomicAdd(&g_cursor[e], 1);
        g_rowmap[slot]  = t;
        g_rowgate[slot] = g_tok_w[t * 2 + k];
    }
}

// ---------------- mma.sync tf32 grouped GEMM ---------------------------------
// Block 128x128, BK=32, 8 warps (4 m x 2 n), warp tile 32x64.
// IS_G2 == 0: H = relu(u[rowmap] @ W1[e] + b1[e])   (K=1024, N=4096)
// IS_G2 == 1: out[tok] += w * (H @ W2[e] + b2[e])   (K=4096, N=1024)
template<int IS_G2>
__global__ __launch_bounds__(256, 2) void k_gemm_mma(
    const float* __restrict__ Aglob,
    const float* __restrict__ Wglob,
    const float* __restrict__ bglob,
    float* __restrict__ out)
{
    constexpr int BM = 128, BN = 128, BK = 32;
    constexpr int LDA = BK + 4;     // 36 floats
    constexpr int LDB = BN + 4;     // 132 floats
    constexpr int NLD  = IS_G2 ? DIM : HID;   // W leading dim == bias dim
    constexpr int KTOT = IS_G2 ? HID : DIM;
    constexpr int KCH  = KTOT / BK;
    constexpr int ALDIM = IS_G2 ? HID : DIM;  // A row length
    constexpr size_t ABY = (size_t)BM * LDA;  // floats per A buffer
    constexpr size_t BBY = (size_t)BK * LDB;  // floats per B buffer

    extern __shared__ float sm[];
    float* s_bias = sm;                 // BN
    float* As     = sm + BN;            // 2 * BM * LDA
    float* Bs     = As + 2 * ABY;       // 2 * BK * LDB

    const int e    = blockIdx.z;
    const int base = g_offsets[e];
    const int cnt  = g_offsets[e + 1] - base;
    const int m0   = blockIdx.x * BM;
    if (m0 >= cnt) return;
    const int n0   = blockIdx.y * BN;

    const int tid  = threadIdx.x;
    const int lane = tid & 31, wid = tid >> 5;
    const int wm = wid & 3, wn = wid >> 2;
    const int g = lane >> 2, tg = lane & 3;

    const float* W = Wglob + (size_t)e * KTOT * NLD;

    if (tid < BN) s_bias[tid] = bglob[(size_t)e * NLD + n0 + tid];

    // per-thread load slots (fixed across chunks)
    const float* asrc[4];
    uint32_t     adst[4];
    #pragma unroll
    for (int j = 0; j < 4; j++) {
        int idx = tid + 256 * j;              // 0..1023
        int r = idx >> 3, kq = idx & 7;       // row 0..127, k-quad 0..7
        int slot = base + m0 + r;
        if (slot > MAXROWS - 1) slot = MAXROWS - 1;
        if (IS_G2) asrc[j] = Aglob + (size_t)slot * ALDIM + kq * 4;
        else       asrc[j] = Aglob + (size_t)g_rowmap[slot] * ALDIM + kq * 4;
        adst[j] = smem_u32(As + r * LDA + kq * 4);
    }
    const float* bsrc[4];
    uint32_t     bdst[4];
    #pragma unroll
    for (int j = 0; j < 4; j++) {
        int idx = tid + 256 * j;
        int k = idx >> 5, nq = idx & 31;      // k 0..31, n-quad 0..31
        bsrc[j] = W + (size_t)k * NLD + n0 + nq * 4;
        bdst[j] = smem_u32(Bs + k * LDB + nq * 4);
    }

    float acc[2][8][4] = {};

    // prefetch chunk 0
    {
        #pragma unroll
        for (int j = 0; j < 4; j++) CP16(adst[j], asrc[j]);
        #pragma unroll
        for (int j = 0; j < 4; j++) CP16(bdst[j], bsrc[j]);
        CP_COMMIT();
    }

    for (int c = 0; c < KCH; c++) {
        if (c + 1 < KCH) {
            const int buf = (c + 1) & 1;
            const int k0 = (c + 1) * BK;
            #pragma unroll
            for (int j = 0; j < 4; j++)
                CP16(adst[j] + (uint32_t)(buf * ABY * 4), asrc[j] + k0);
            #pragma unroll
            for (int j = 0; j < 4; j++)
                CP16(bdst[j] + (uint32_t)(buf * BBY * 4), bsrc[j] + (size_t)k0 * NLD);
        }
        CP_COMMIT();
        CP_WAIT1();
        __syncthreads();

        const float* Ab = As + (c & 1) * ABY;
        const float* Bb = Bs + (c & 1) * BBY;

        #pragma unroll
        for (int ks = 0; ks < 4; ks++) {
            const int kc = ks * 8 + tg;
            uint32_t au[2][4], bu[8][2];
            #pragma unroll
            for (int mi = 0; mi < 2; mi++) {
                const int r0 = wm * 32 + mi * 16 + g;
                au[mi][0] = tf32u(Ab[r0 * LDA + kc]);
                au[mi][1] = tf32u(Ab[(r0 + 8) * LDA + kc]);
                au[mi][2] = tf32u(Ab[r0 * LDA + kc + 4]);
                au[mi][3] = tf32u(Ab[(r0 + 8) * LDA + kc + 4]);
            }
            #pragma unroll
            for (int ni = 0; ni < 8; ni++) {
                const int bn = wn * 64 + ni * 8 + g;
                bu[ni][0] = tf32u(Bb[kc * LDB + bn]);
                bu[ni][1] = tf32u(Bb[(kc + 4) * LDB + bn]);
            }
            #pragma unroll
            for (int mi = 0; mi < 2; mi++)
                #pragma unroll
                for (int ni = 0; ni < 8; ni++)
                    MMA_TF32(acc[mi][ni], au[mi], bu[ni]);
        }
        __syncthreads();
    }
    CP_WAITALL();

    // ---------------- epilogue ----------------
    #pragma unroll
    for (int mi = 0; mi < 2; mi++) {
        #pragma unroll
        for (int half = 0; half < 2; half++) {
            const int rl = wm * 32 + mi * 16 + half * 8 + g;   // local row
            const bool valid = (m0 + rl) < cnt;
            if (!valid) continue;
            const int slot = base + m0 + rl;
            if (IS_G2) {
                const int   tok = g_rowmap[slot];
                const float wgt = g_rowgate[slot];
                float* orow = out + (size_t)tok * DIM + n0;
                #pragma unroll
                for (int ni = 0; ni < 8; ni++) {
                    const int cl = wn * 64 + ni * 8 + tg * 2;
                    const float v0 = acc[mi][ni][half * 2 + 0] + s_bias[cl];
                    const float v1 = acc[mi][ni][half * 2 + 1] + s_bias[cl + 1];
                    atomicAdd(orow + cl,     wgt * v0);
                    atomicAdd(orow + cl + 1, wgt * v1);
                }
            } else {
                float* hrow = g_H + (size_t)slot * HID + n0;
                #pragma unroll
                for (int ni = 0; ni < 8; ni++) {
                    const int cl = wn * 64 + ni * 8 + tg * 2;
                    float2 v;
                    v.x = fmaxf(acc[mi][ni][half * 2 + 0] + s_bias[cl], 0.f);
                    v.y = fmaxf(acc[mi][ni][half * 2 + 1] + s_bias[cl + 1], 0.f);
                    *(float2*)(hrow + cl) = v;
                }
            }
        }
    }
}

// ---------------- launch -----------------------------------------------------
extern "C" void kernel_launch(void* const* d_in, const int* in_sizes, int n_in,
                              void* d_out, int out_size)
{
    const float* u    = (const float*)d_in[0];
    const float* cent = (const float*)d_in[1];
    const float* bias = (const float*)d_in[2];
    const float* W1   = (const float*)d_in[3];
    const float* b1   = (const float*)d_in[4];
    const float* W2   = (const float*)d_in[5];
    const float* b2   = (const float*)d_in[6];
    float* out = (float*)d_out;

    float* maxvio_ptr;
    if (out_size > T_TOK * DIM) {
        maxvio_ptr = out + (size_t)T_TOK * DIM;
    } else {
        cudaGetSymbolAddress((void**)&maxvio_ptr, g_dummy);
    }
    float* hbuf;
    cudaGetSymbolAddress((void**)&hbuf, g_H);

    // smem: BN + 2*BM*LDA + 2*BK*LDB floats = 128 + 9216 + 8448 = 17792 floats
    const int SMEM = 17792 * 4;   // 71168 B
    cudaFuncSetAttribute(k_gemm_mma<0>, cudaFuncAttributeMaxDynamicSharedMemorySize, SMEM);
    cudaFuncSetAttribute(k_gemm_mma<1>, cudaFuncAttributeMaxDynamicSharedMemorySize, SMEM);

    k_zero<<<(T_TOK * DIM / 4 + 255) / 256, 256>>>(out);
    k_router<<<T_TOK, 256>>>(u, cent, bias);
    k_offsets<<<1, 32>>>(maxvio_ptr);
    k_scatter<<<(T_TOK + 255) / 256, 256>>>();
    // max rows per expert is T_TOK (top-2 distinct experts) -> <= 16 M-tiles
    k_gemm_mma<0><<<dim3(16, HID / 128, NEXP), 256, SMEM>>>(u, W1, b1, nullptr);
    k_gemm_mma<1><<<dim3(16, DIM / 128, NEXP), 256, SMEM>>>(hbuf, W2, b2, out);
}

// round 4
// speedup vs baseline: 3.6974x; 1.0028x over previous
#include <cuda_runtime.h>
#include <cstdint>
#include <math.h>

#define T_TOK   2048
#define DIM     1024
#define NEXP    8
#define HID     4096
#define TOPK    2
#define MAXROWS (T_TOK * TOPK)   // 4096

// ---------------- scratch (__device__ globals) -------------------------------
__device__ float g_H[(size_t)MAXROWS * HID];   // 64 MB hidden acts (tf32-rounded)
__device__ float g_U[(size_t)T_TOK * DIM];     // 8 MB tf32-rounded inputs
__device__ float g_O[(size_t)MAXROWS * DIM];   // 16 MB expert outputs
__device__ int   g_rowmap[MAXROWS];            // slot -> token
__device__ int   g_counts[NEXP];
__device__ int   g_offsets[NEXP + 1];
__device__ int   g_tok_e[T_TOK * TOPK];
__device__ float g_tok_w[T_TOK * TOPK];
__device__ int   g_tok_slot[T_TOK * TOPK];
__device__ float g_dummy[1];

// ---------------- helpers ----------------------------------------------------
__device__ __forceinline__ uint32_t smem_u32(const void* p) {
    uint32_t a;
    asm("{ .reg .u64 t; cvta.to.shared.u64 t, %1; cvt.u32.u64 %0, t; }"
        : "=r"(a) : "l"(p));
    return a;
}
__device__ __forceinline__ float tf32r(float x) {
    float r;
    asm("cvt.rna.tf32.f32 %0, %1;" : "=f"(r) : "f"(x));
    return r;
}
__device__ __forceinline__ uint32_t tf32u(float x) {
    return __float_as_uint(tf32r(x));
}

#define CP16(dst, src) \
    asm volatile("cp.async.cg.shared.global [%0], [%1], 16;" :: "r"(dst), "l"(src))
#define CP_COMMIT()  asm volatile("cp.async.commit_group;" ::: "memory")
#define CP_WAIT2()   asm volatile("cp.async.wait_group 2;" ::: "memory")
#define CP_WAITALL() asm volatile("cp.async.wait_all;" ::: "memory")

#define LDSM_X4(r, addr) \
    asm volatile("ldmatrix.sync.aligned.m8n8.x4.shared.b16 {%0,%1,%2,%3}, [%4];" \
        : "=r"((r)[0]), "=r"((r)[1]), "=r"((r)[2]), "=r"((r)[3]) : "r"(addr))

#define MMA_TF32(d, a, b) \
    asm volatile("mma.sync.aligned.m16n8k8.row.col.f32.tf32.tf32.f32 " \
        "{%0,%1,%2,%3}, {%4,%5,%6,%7}, {%8,%9}, {%0,%1,%2,%3};" \
        : "+f"((d)[0]), "+f"((d)[1]), "+f"((d)[2]), "+f"((d)[3]) \
        : "r"((a)[0]), "r"((a)[1]), "r"((a)[2]), "r"((a)[3]), \
          "r"((b)[0]), "r"((b)[1]))

// ---------------- K0: round u -> g_U, reset counters -------------------------
__global__ void k_prep(const float* __restrict__ u)
{
    size_t i = ((size_t)blockIdx.x * blockDim.x + threadIdx.x) * 4;
    if (i < (size_t)T_TOK * DIM) {
        float4 v = *(const float4*)(u + i);
        v.x = tf32r(v.x); v.y = tf32r(v.y); v.z = tf32r(v.z); v.w = tf32r(v.w);
        *(float4*)(g_U + i) = v;
    }
    if (blockIdx.x == 0 && threadIdx.x < NEXP) g_counts[threadIdx.x] = 0;
}

// ---------------- K1: router -------------------------------------------------
__global__ void k_router(const float* __restrict__ u,
                         const float* __restrict__ cent,
                         const float* __restrict__ bias)
{
    int t    = blockIdx.x;
    int warp = threadIdx.x >> 5;
    int lane = threadIdx.x & 31;

    const float* ur = u + (size_t)t * DIM;
    const float* cr = cent + (size_t)warp * DIM;

    float s = 0.f;
    #pragma unroll 8
    for (int i = lane; i < DIM; i += 32) s += ur[i] * cr[i];
    #pragma unroll
    for (int o = 16; o; o >>= 1) s += __shfl_xor_sync(0xffffffffu, s, o);

    __shared__ float sc[NEXP];
    if (lane == 0) sc[warp] = s + bias[warp];
    __syncthreads();

    if (threadIdx.x == 0) {
        float m = sc[0];
        #pragma unroll
        for (int e = 1; e < NEXP; e++) m = fmaxf(m, sc[e]);
        float p[NEXP];
        float den = 0.f;
        #pragma unroll
        for (int e = 0; e < NEXP; e++) { p[e] = __expf(sc[e] - m); den += p[e]; }

        int e0 = 0;
        #pragma unroll
        for (int e = 1; e < NEXP; e++) if (p[e] > p[e0]) e0 = e;
        int e1 = (e0 == 0) ? 1 : 0;
        #pragma unroll
        for (int e = 0; e < NEXP; e++) if (e != e0 && p[e] > p[e1]) e1 = e;

        float inv = 1.f / den;
        g_tok_e[t * 2 + 0] = e0;  g_tok_w[t * 2 + 0] = p[e0] * inv;
        g_tok_e[t * 2 + 1] = e1;  g_tok_w[t * 2 + 1] = p[e1] * inv;
        atomicAdd(&g_counts[e0], 1);
        atomicAdd(&g_counts[e1], 1);
    }
}

// ---------------- K2: fused offsets + maxvio + scatter (single block) --------
__global__ void k_offscatter(float* __restrict__ maxvio_out)
{
    __shared__ int s_off[NEXP];
    __shared__ int s_cur[NEXP];
    int tid = threadIdx.x;
    if (tid < NEXP) s_cur[tid] = 0;
    if (tid == 0) {
        int off = 0, mx = 0;
        #pragma unroll
        for (int e = 0; e < NEXP; e++) {
            s_off[e] = off;
            g_offsets[e] = off;
            int c = g_counts[e];
            off += c;
            if (c > mx) mx = c;
        }
        g_offsets[NEXP] = off;
        const float perfect = (float)(TOPK * T_TOK) / (float)NEXP;
        *maxvio_out = ((float)mx - perfect) / perfect;
    }
    __syncthreads();
    for (int t = tid; t < T_TOK; t += blockDim.x) {
        #pragma unroll
        for (int k = 0; k < TOPK; k++) {
            int e = g_tok_e[t * 2 + k];
            int slot = s_off[e] + atomicAdd(&s_cur[e], 1);
            g_rowmap[slot] = t;
            g_tok_slot[t * 2 + k] = slot;
        }
    }
}

// ---------------- mma.sync tf32 grouped GEMM ---------------------------------
// Block 128x128, BK=32, 3-stage cp.async, 8 warps (4m x 2n), warp tile 32x64.
// IS_G2 == 0: g_H[slot] = relu_tf32(g_U[rowmap] @ W1[e] + b1[e])  (K=1024, N=4096)
// IS_G2 == 1: g_O[slot] = g_H[slot] @ W2[e]                        (K=4096, N=1024)
template<int IS_G2>
__global__ __launch_bounds__(256, 2) void k_gemm_mma(
    const float* __restrict__ Aglob,
    const float* __restrict__ Wglob,
    const float* __restrict__ bglob)
{
    constexpr int BM = 128, BN = 128, BK = 32, ST = 3;
    constexpr int LDA = BK + 4;               // 36 floats (rows 16B-aligned)
    constexpr int LDB = BN + 4;               // 132 floats
    constexpr int NLD   = IS_G2 ? DIM : HID;
    constexpr int KTOT  = IS_G2 ? HID : DIM;
    constexpr int KCH   = KTOT / BK;
    constexpr int ALDIM = IS_G2 ? HID : DIM;
    constexpr int ABY = BM * LDA;             // floats per A stage
    constexpr int BBY = BK * LDB;             // floats per B stage

    extern __shared__ float sm[];
    float* s_bias = sm;                       // BN
    float* As     = sm + BN;                  // ST * ABY
    float* Bs     = As + ST * ABY;            // ST * BBY

    const int e    = blockIdx.z;
    const int base = g_offsets[e];
    const int cnt  = g_offsets[e + 1] - base;
    const int m0   = blockIdx.x * BM;
    if (m0 >= cnt) return;
    const int n0   = blockIdx.y * BN;

    const int tid  = threadIdx.x;
    const int lane = tid & 31, wid = tid >> 5;
    const int wm = wid & 3, wn = wid >> 2;
    const int g = lane >> 2, tg = lane & 3;

    const float* W = Wglob + (size_t)e * (size_t)KTOT * NLD;

    if (!IS_G2 && tid < BN) s_bias[tid] = bglob[(size_t)e * NLD + n0 + tid];

    // per-thread cp.async slots
    const float* asrc[4];
    uint32_t     adst[4];
    #pragma unroll
    for (int j = 0; j < 4; j++) {
        int idx = tid + 256 * j;              // 0..1023
        int r = idx >> 3, kq = idx & 7;
        int slot = base + m0 + r;
        if (slot > MAXROWS - 1) slot = MAXROWS - 1;
        if (IS_G2) asrc[j] = Aglob + (size_t)slot * ALDIM + kq * 4;
        else       asrc[j] = Aglob + (size_t)g_rowmap[slot] * ALDIM + kq * 4;
        adst[j] = smem_u32(As + r * LDA + kq * 4);
    }
    const float* bsrc[4];
    uint32_t     bdst[4];
    #pragma unroll
    for (int j = 0; j < 4; j++) {
        int idx = tid + 256 * j;
        int k = idx >> 5, nq = idx & 31;
        bsrc[j] = W + (size_t)k * NLD + n0 + nq * 4;
        bdst[j] = smem_u32(Bs + k * LDB + nq * 4);
    }

    // ldmatrix per-thread base addresses for A fragments (mi = 0,1)
    uint32_t amat[2];
    {
        int sector = lane >> 3, rowin = lane & 7;
        #pragma unroll
        for (int mi = 0; mi < 2; mi++) {
            int rloc = wm * 32 + mi * 16 + (sector & 1) * 8 + rowin;
            int colb = (sector >> 1) * 4;
            amat[mi] = smem_u32(As + rloc * LDA + colb);
        }
    }

    float acc[2][8][4] = {};

    // prologue: prefetch chunks 0 and 1
    #pragma unroll
    for (int pc = 0; pc < 2; pc++) {
        const uint32_t so = (uint32_t)(pc * ABY * 4);
        const uint32_t sob = (uint32_t)(pc * BBY * 4);
        const int k0 = pc * BK;
        #pragma unroll
        for (int j = 0; j < 4; j++) CP16(adst[j] + so, asrc[j] + k0);
        #pragma unroll
        for (int j = 0; j < 4; j++) CP16(bdst[j] + sob, bsrc[j] + (size_t)k0 * NLD);
        CP_COMMIT();
    }

    int buf = 0, nbuf = 2;
    for (int c = 0; c < KCH; c++) {
        __syncthreads();   // everyone done with the buffer we are about to refill
        if (c + 2 < KCH) {
            const uint32_t so  = (uint32_t)(nbuf * ABY * 4);
            const uint32_t sob = (uint32_t)(nbuf * BBY * 4);
            const int k0 = (c + 2) * BK;
            #pragma unroll
            for (int j = 0; j < 4; j++) CP16(adst[j] + so, asrc[j] + k0);
            #pragma unroll
            for (int j = 0; j < 4; j++) CP16(bdst[j] + sob, bsrc[j] + (size_t)k0 * NLD);
        }
        CP_COMMIT();
        CP_WAIT2();        // chunk c resident
        __syncthreads();

        const float* Bb = Bs + buf * BBY;
        const uint32_t abufoff = (uint32_t)(buf * ABY * 4);

        #pragma unroll
        for (int ks = 0; ks < 4; ks++) {
            const int kc = ks * 8 + tg;
            uint32_t au[2][4], bu[8][2];
            #pragma unroll
            for (int mi = 0; mi < 2; mi++)
                LDSM_X4(au[mi], amat[mi] + abufoff + (uint32_t)(ks * 32));
            #pragma unroll
            for (int ni = 0; ni < 8; ni++) {
                const int bn = wn * 64 + ni * 8 + g;
                bu[ni][0] = tf32u(Bb[kc * LDB + bn]);
                bu[ni][1] = tf32u(Bb[(kc + 4) * LDB + bn]);
            }
            #pragma unroll
            for (int mi = 0; mi < 2; mi++)
                #pragma unroll
                for (int ni = 0; ni < 8; ni++)
                    MMA_TF32(acc[mi][ni], au[mi], bu[ni]);
        }
        buf = (buf + 1 == ST) ? 0 : buf + 1;
        nbuf = (nbuf + 1 == ST) ? 0 : nbuf + 1;
    }
    CP_WAITALL();

    // ---------------- epilogue ----------------
    #pragma unroll
    for (int mi = 0; mi < 2; mi++) {
        #pragma unroll
        for (int half = 0; half < 2; half++) {
            const int rl = wm * 32 + mi * 16 + half * 8 + g;
            if ((m0 + rl) >= cnt) continue;
            const int slot = base + m0 + rl;
            if (IS_G2) {
                float* orow = g_O + (size_t)slot * DIM + n0;
                #pragma unroll
                for (int ni = 0; ni < 8; ni++) {
                    const int cl = wn * 64 + ni * 8 + tg * 2;
                    float2 v;
                    v.x = acc[mi][ni][half * 2 + 0];
                    v.y = acc[mi][ni][half * 2 + 1];
                    *(float2*)(orow + cl) = v;
                }
            } else {
                float* hrow = g_H + (size_t)slot * HID + n0;
                #pragma unroll
                for (int ni = 0; ni < 8; ni++) {
                    const int cl = wn * 64 + ni * 8 + tg * 2;
                    float2 v;
                    v.x = tf32r(fmaxf(acc[mi][ni][half * 2 + 0] + s_bias[cl], 0.f));
                    v.y = tf32r(fmaxf(acc[mi][ni][half * 2 + 1] + s_bias[cl + 1], 0.f));
                    *(float2*)(hrow + cl) = v;
                }
            }
        }
    }
}

// ---------------- K5: combine out[t] = sum_k w_k * (o_k + b2[e_k]) ----------
__global__ void k_combine(const float* __restrict__ b2, float* __restrict__ out)
{
    int t = blockIdx.x;
    int d = threadIdx.x * 4;
    int e0 = g_tok_e[t * 2], e1 = g_tok_e[t * 2 + 1];
    float w0 = g_tok_w[t * 2], w1 = g_tok_w[t * 2 + 1];
    int s0 = g_tok_slot[t * 2], s1 = g_tok_slot[t * 2 + 1];

    float4 o0 = *(const float4*)(g_O + (size_t)s0 * DIM + d);
    float4 o1 = *(const float4*)(g_O + (size_t)s1 * DIM + d);
    float4 c0 = *(const float4*)(b2 + (size_t)e0 * DIM + d);
    float4 c1 = *(const float4*)(b2 + (size_t)e1 * DIM + d);

    float4 r;
    r.x = w0 * (o0.x + c0.x) + w1 * (o1.x + c1.x);
    r.y = w0 * (o0.y + c0.y) + w1 * (o1.y + c1.y);
    r.z = w0 * (o0.z + c0.z) + w1 * (o1.z + c1.z);
    r.w = w0 * (o0.w + c0.w) + w1 * (o1.w + c1.w);
    *(float4*)(out + (size_t)t * DIM + d) = r;
}

// ---------------- launch -----------------------------------------------------
extern "C" void kernel_launch(void* const* d_in, const int* in_sizes, int n_in,
                              void* d_out, int out_size)
{
    const float* u    = (const float*)d_in[0];
    const float* cent = (const float*)d_in[1];
    const float* bias = (const float*)d_in[2];
    const float* W1   = (const float*)d_in[3];
    const float* b1   = (const float*)d_in[4];
    const float* W2   = (const float*)d_in[5];
    const float* b2   = (const float*)d_in[6];
    float* out = (float*)d_out;

    float* maxvio_ptr;
    if (out_size > T_TOK * DIM) {
        maxvio_ptr = out + (size_t)T_TOK * DIM;
    } else {
        cudaGetSymbolAddress((void**)&maxvio_ptr, g_dummy);
    }
    float* uruf;  cudaGetSymbolAddress((void**)&uruf, g_U);
    float* hbuf;  cudaGetSymbolAddress((void**)&hbuf, g_H);

    // smem: 128 + 3*128*36 + 3*32*132 = 26624 floats = 106496 B
    const int SMEM = 26624 * 4;
    cudaFuncSetAttribute(k_gemm_mma<0>, cudaFuncAttributeMaxDynamicSharedMemorySize, SMEM);
    cudaFuncSetAttribute(k_gemm_mma<1>, cudaFuncAttributeMaxDynamicSharedMemorySize, SMEM);

    k_prep<<<(T_TOK * DIM / 4 + 255) / 256, 256>>>(u);           // idx 0
    k_router<<<T_TOK, 256>>>(u, cent, bias);                     // idx 1
    k_offscatter<<<1, 1024>>>(maxvio_ptr);                       // idx 2
    k_gemm_mma<0><<<dim3(16, HID / 128, NEXP), 256, SMEM>>>(uruf, W1, b1);  // idx 3
    k_gemm_mma<1><<<dim3(16, DIM / 128, NEXP), 256, SMEM>>>(hbuf, W2, b2);  // idx 4
    k_combine<<<T_TOK, 256>>>(b2, out);                          // idx 5
}

// round 5
// speedup vs baseline: 4.1938x; 1.1343x over previous
#include <cuda_runtime.h>
#include <cstdint>
#include <math.h>

#define T_TOK   2048
#define DIM     1024
#define NEXP    8
#define HID     4096
#define TOPK    2
#define MAXROWS (T_TOK * TOPK)   // 4096

// ---------------- scratch (__device__ globals) -------------------------------
__device__ float g_H[(size_t)MAXROWS * HID];   // 64 MB hidden acts (tf32-rounded)
__device__ float g_U[(size_t)T_TOK * DIM];     // 8 MB tf32-rounded inputs
__device__ float g_O[(size_t)MAXROWS * DIM];   // 16 MB expert outputs
__device__ int   g_rowmap[MAXROWS];            // slot -> token
__device__ int   g_counts[NEXP];
__device__ int   g_offsets[NEXP + 1];
__device__ int   g_tok_e[T_TOK * TOPK];
__device__ float g_tok_w[T_TOK * TOPK];
__device__ int   g_tok_slot[T_TOK * TOPK];
__device__ float g_dummy[1];

// ---------------- helpers ----------------------------------------------------
__device__ __forceinline__ uint32_t smem_u32(const void* p) {
    uint32_t a;
    asm("{ .reg .u64 t; cvta.to.shared.u64 t, %1; cvt.u32.u64 %0, t; }"
        : "=r"(a) : "l"(p));
    return a;
}
__device__ __forceinline__ float tf32r(float x) {
    float r;
    asm("cvt.rna.tf32.f32 %0, %1;" : "=f"(r) : "f"(x));
    return r;
}
__device__ __forceinline__ uint32_t tf32u(float x) {
    return __float_as_uint(tf32r(x));
}

#define CP16(dst, src) \
    asm volatile("cp.async.cg.shared.global [%0], [%1], 16;" :: "r"(dst), "l"(src))
#define CP_COMMIT()  asm volatile("cp.async.commit_group;" ::: "memory")
#define CP_WAIT1()   asm volatile("cp.async.wait_group 1;" ::: "memory")
#define CP_WAITALL() asm volatile("cp.async.wait_all;" ::: "memory")

#define LDSM_X4(r, addr) \
    asm volatile("ldmatrix.sync.aligned.m8n8.x4.shared.b16 {%0,%1,%2,%3}, [%4];" \
        : "=r"((r)[0]), "=r"((r)[1]), "=r"((r)[2]), "=r"((r)[3]) : "r"(addr))

#define MMA_TF32(d, a, b) \
    asm volatile("mma.sync.aligned.m16n8k8.row.col.f32.tf32.tf32.f32 " \
        "{%0,%1,%2,%3}, {%4,%5,%6,%7}, {%8,%9}, {%0,%1,%2,%3};" \
        : "+f"((d)[0]), "+f"((d)[1]), "+f"((d)[2]), "+f"((d)[3]) \
        : "r"((a)[0]), "r"((a)[1]), "r"((a)[2]), "r"((a)[3]), \
          "r"((b)[0]), "r"((b)[1]))

// ---------------- K0: round u -> g_U, reset counters -------------------------
__global__ void k_prep(const float* __restrict__ u)
{
    size_t i = ((size_t)blockIdx.x * blockDim.x + threadIdx.x) * 4;
    if (i < (size_t)T_TOK * DIM) {
        float4 v = *(const float4*)(u + i);
        v.x = tf32r(v.x); v.y = tf32r(v.y); v.z = tf32r(v.z); v.w = tf32r(v.w);
        *(float4*)(g_U + i) = v;
    }
    if (blockIdx.x == 0 && threadIdx.x < NEXP) g_counts[threadIdx.x] = 0;
}

// ---------------- K1: router -------------------------------------------------
__global__ void k_router(const float* __restrict__ u,
                         const float* __restrict__ cent,
                         const float* __restrict__ bias)
{
    int t    = blockIdx.x;
    int warp = threadIdx.x >> 5;
    int lane = threadIdx.x & 31;

    const float* ur = u + (size_t)t * DIM;
    const float* cr = cent + (size_t)warp * DIM;

    float s = 0.f;
    #pragma unroll 8
    for (int i = lane; i < DIM; i += 32) s += ur[i] * cr[i];
    #pragma unroll
    for (int o = 16; o; o >>= 1) s += __shfl_xor_sync(0xffffffffu, s, o);

    __shared__ float sc[NEXP];
    if (lane == 0) sc[warp] = s + bias[warp];
    __syncthreads();

    if (threadIdx.x == 0) {
        float m = sc[0];
        #pragma unroll
        for (int e = 1; e < NEXP; e++) m = fmaxf(m, sc[e]);
        float p[NEXP];
        float den = 0.f;
        #pragma unroll
        for (int e = 0; e < NEXP; e++) { p[e] = __expf(sc[e] - m); den += p[e]; }

        int e0 = 0;
        #pragma unroll
        for (int e = 1; e < NEXP; e++) if (p[e] > p[e0]) e0 = e;
        int e1 = (e0 == 0) ? 1 : 0;
        #pragma unroll
        for (int e = 0; e < NEXP; e++) if (e != e0 && p[e] > p[e1]) e1 = e;

        float inv = 1.f / den;
        g_tok_e[t * 2 + 0] = e0;  g_tok_w[t * 2 + 0] = p[e0] * inv;
        g_tok_e[t * 2 + 1] = e1;  g_tok_w[t * 2 + 1] = p[e1] * inv;
        atomicAdd(&g_counts[e0], 1);
        atomicAdd(&g_counts[e1], 1);
    }
}

// ---------------- K2: fused offsets + maxvio + scatter (single block) --------
__global__ void k_offscatter(float* __restrict__ maxvio_out)
{
    __shared__ int s_off[NEXP];
    __shared__ int s_cur[NEXP];
    int tid = threadIdx.x;
    if (tid < NEXP) s_cur[tid] = 0;
    if (tid == 0) {
        int off = 0, mx = 0;
        #pragma unroll
        for (int e = 0; e < NEXP; e++) {
            s_off[e] = off;
            g_offsets[e] = off;
            int c = g_counts[e];
            off += c;
            if (c > mx) mx = c;
        }
        g_offsets[NEXP] = off;
        const float perfect = (float)(TOPK * T_TOK) / (float)NEXP;
        *maxvio_out = ((float)mx - perfect) / perfect;
    }
    __syncthreads();
    for (int t = tid; t < T_TOK; t += blockDim.x) {
        #pragma unroll
        for (int k = 0; k < TOPK; k++) {
            int e = g_tok_e[t * 2 + k];
            int slot = s_off[e] + atomicAdd(&s_cur[e], 1);
            g_rowmap[slot] = t;
            g_tok_slot[t * 2 + k] = slot;
        }
    }
}

// ---------------- mma.sync tf32 grouped GEMM ---------------------------------
// Block 128x128, BK=32, 3-stage cp.async (single sync per chunk),
// 8 warps (2m x 4n), warp tile 64x32.
// IS_G2 == 0: g_H[slot] = relu_tf32(g_U[rowmap] @ W1[e] + b1[e])  (K=1024, N=4096)
// IS_G2 == 1: g_O[slot] = g_H[slot] @ W2[e]                        (K=4096, N=1024)
template<int IS_G2>
__global__ __launch_bounds__(256, 2) void k_gemm_mma(
    const float* __restrict__ Aglob,
    const float* __restrict__ Wglob,
    const float* __restrict__ bglob)
{
    constexpr int BM = 128, BN = 128, BK = 32, ST = 3;
    constexpr int LDA = BK + 4;               // 36 floats; ldmatrix rows conflict-free
    constexpr int LDB = BN + 8;               // 136 floats; 4 k-rows at bank offsets 0/8/16/24
    constexpr int NLD   = IS_G2 ? DIM : HID;
    constexpr int KTOT  = IS_G2 ? HID : DIM;
    constexpr int KCH   = KTOT / BK;
    constexpr int ALDIM = IS_G2 ? HID : DIM;
    constexpr int ABY = BM * LDA;             // floats per A stage
    constexpr int BBY = BK * LDB;             // floats per B stage

    extern __shared__ float sm[];
    float* s_bias = sm;                       // BN
    float* As     = sm + BN;                  // ST * ABY
    float* Bs     = As + ST * ABY;            // ST * BBY

    const int e    = blockIdx.z;
    const int base = g_offsets[e];
    const int cnt  = g_offsets[e + 1] - base;
    const int m0   = blockIdx.x * BM;
    if (m0 >= cnt) return;
    const int n0   = blockIdx.y * BN;

    const int tid  = threadIdx.x;
    const int lane = tid & 31, wid = tid >> 5;
    const int wm = wid & 1, wn = wid >> 1;    // 2 m-warps x 4 n-warps
    const int g = lane >> 2, tg = lane & 3;

    const float* W = Wglob + (size_t)e * (size_t)KTOT * NLD;

    if (!IS_G2 && tid < BN) s_bias[tid] = bglob[(size_t)e * NLD + n0 + tid];

    // per-thread cp.async slots
    const float* asrc[4];
    uint32_t     adst[4];
    #pragma unroll
    for (int j = 0; j < 4; j++) {
        int idx = tid + 256 * j;              // 0..1023
        int r = idx >> 3, kq = idx & 7;
        int slot = base + m0 + r;
        if (slot > MAXROWS - 1) slot = MAXROWS - 1;
        if (IS_G2) asrc[j] = Aglob + (size_t)slot * ALDIM + kq * 4;
        else       asrc[j] = Aglob + (size_t)g_rowmap[slot] * ALDIM + kq * 4;
        adst[j] = smem_u32(As + r * LDA + kq * 4);
    }
    const float* bsrc[4];
    uint32_t     bdst[4];
    #pragma unroll
    for (int j = 0; j < 4; j++) {
        int idx = tid + 256 * j;
        int k = idx >> 5, nq = idx & 31;
        bsrc[j] = W + (size_t)k * NLD + n0 + nq * 4;
        bdst[j] = smem_u32(Bs + k * LDB + nq * 4);
    }

    // ldmatrix per-thread base addresses for A fragments (mi = 0..3)
    uint32_t amat[4];
    {
        int sector = lane >> 3, rowin = lane & 7;
        #pragma unroll
        for (int mi = 0; mi < 4; mi++) {
            int rloc = wm * 64 + mi * 16 + (sector & 1) * 8 + rowin;
            int colb = (sector >> 1) * 4;
            amat[mi] = smem_u32(As + rloc * LDA + colb);
        }
    }

    float acc[4][4][4] = {};

    // prologue: prefetch chunks 0 and 1
    #pragma unroll
    for (int pc = 0; pc < ST - 1; pc++) {
        const uint32_t so  = (uint32_t)(pc * ABY * 4);
        const uint32_t sob = (uint32_t)(pc * BBY * 4);
        const int k0 = pc * BK;
        #pragma unroll
        for (int j = 0; j < 4; j++) CP16(adst[j] + so, asrc[j] + k0);
        #pragma unroll
        for (int j = 0; j < 4; j++) CP16(bdst[j] + sob, bsrc[j] + (size_t)k0 * NLD);
        CP_COMMIT();
    }

    for (int c = 0; c < KCH; c++) {
        CP_WAIT1();          // chunk c resident (ST-2 = 1 group pending)
        __syncthreads();     // visibility of chunk c + all readers done with buf (c-1)%ST

        // refill buffer (c+ST-1)%ST == (c-1+ST)%ST, read 2 iterations from now
        const int wb = (c + ST - 1) % ST;
        if (c + ST - 1 < KCH) {
            const uint32_t so  = (uint32_t)(wb * ABY * 4);
            const uint32_t sob = (uint32_t)(wb * BBY * 4);
            const int k0 = (c + ST - 1) * BK;
            #pragma unroll
            for (int j = 0; j < 4; j++) CP16(adst[j] + so, asrc[j] + k0);
            #pragma unroll
            for (int j = 0; j < 4; j++) CP16(bdst[j] + sob, bsrc[j] + (size_t)k0 * NLD);
        }
        CP_COMMIT();

        const int buf = c % ST;
        const float* Bb = Bs + buf * BBY;
        const uint32_t abufoff = (uint32_t)(buf * ABY * 4);

        #pragma unroll
        for (int ks = 0; ks < 4; ks++) {
            const int kc = ks * 8 + tg;
            uint32_t au[4][4], bu[4][2];
            #pragma unroll
            for (int mi = 0; mi < 4; mi++)
                LDSM_X4(au[mi], amat[mi] + abufoff + (uint32_t)(ks * 32));
            #pragma unroll
            for (int ni = 0; ni < 4; ni++) {
                const int bn = wn * 32 + ni * 8 + g;
                bu[ni][0] = tf32u(Bb[kc * LDB + bn]);
                bu[ni][1] = tf32u(Bb[(kc + 4) * LDB + bn]);
            }
            #pragma unroll
            for (int mi = 0; mi < 4; mi++)
                #pragma unroll
                for (int ni = 0; ni < 4; ni++)
                    MMA_TF32(acc[mi][ni], au[mi], bu[ni]);
        }
    }
    CP_WAITALL();

    // ---------------- epilogue ----------------
    #pragma unroll
    for (int mi = 0; mi < 4; mi++) {
        #pragma unroll
        for (int half = 0; half < 2; half++) {
            const int rl = wm * 64 + mi * 16 + half * 8 + g;
            if ((m0 + rl) >= cnt) continue;
            const int slot = base + m0 + rl;
            if (IS_G2) {
                float* orow = g_O + (size_t)slot * DIM + n0;
                #pragma unroll
                for (int ni = 0; ni < 4; ni++) {
                    const int cl = wn * 32 + ni * 8 + tg * 2;
                    float2 v;
                    v.x = acc[mi][ni][half * 2 + 0];
                    v.y = acc[mi][ni][half * 2 + 1];
                    *(float2*)(orow + cl) = v;
                }
            } else {
                float* hrow = g_H + (size_t)slot * HID + n0;
                #pragma unroll
                for (int ni = 0; ni < 4; ni++) {
                    const int cl = wn * 32 + ni * 8 + tg * 2;
                    float2 v;
                    v.x = tf32r(fmaxf(acc[mi][ni][half * 2 + 0] + s_bias[cl], 0.f));
                    v.y = tf32r(fmaxf(acc[mi][ni][half * 2 + 1] + s_bias[cl + 1], 0.f));
                    *(float2*)(hrow + cl) = v;
                }
            }
        }
    }
}

// ---------------- K5: combine out[t] = sum_k w_k * (o_k + b2[e_k]) ----------
__global__ void k_combine(const float* __restrict__ b2, float* __restrict__ out)
{
    int t = blockIdx.x;
    int d = threadIdx.x * 4;
    int e0 = g_tok_e[t * 2], e1 = g_tok_e[t * 2 + 1];
    float w0 = g_tok_w[t * 2], w1 = g_tok_w[t * 2 + 1];
    int s0 = g_tok_slot[t * 2], s1 = g_tok_slot[t * 2 + 1];

    float4 o0 = *(const float4*)(g_O + (size_t)s0 * DIM + d);
    float4 o1 = *(const float4*)(g_O + (size_t)s1 * DIM + d);
    float4 c0 = *(const float4*)(b2 + (size_t)e0 * DIM + d);
    float4 c1 = *(const float4*)(b2 + (size_t)e1 * DIM + d);

    float4 r;
    r.x = w0 * (o0.x + c0.x) + w1 * (o1.x + c1.x);
    r.y = w0 * (o0.y + c0.y) + w1 * (o1.y + c1.y);
    r.z = w0 * (o0.z + c0.z) + w1 * (o1.z + c1.z);
    r.w = w0 * (o0.w + c0.w) + w1 * (o1.w + c1.w);
    *(float4*)(out + (size_t)t * DIM + d) = r;
}

// ---------------- launch -----------------------------------------------------
extern "C" void kernel_launch(void* const* d_in, const int* in_sizes, int n_in,
                              void* d_out, int out_size)
{
    const float* u    = (const float*)d_in[0];
    const float* cent = (const float*)d_in[1];
    const float* bias = (const float*)d_in[2];
    const float* W1   = (const float*)d_in[3];
    const float* b1   = (const float*)d_in[4];
    const float* W2   = (const float*)d_in[5];
    const float* b2   = (const float*)d_in[6];
    float* out = (float*)d_out;

    float* maxvio_ptr;
    if (out_size > T_TOK * DIM) {
        maxvio_ptr = out + (size_t)T_TOK * DIM;
    } else {
        cudaGetSymbolAddress((void**)&maxvio_ptr, g_dummy);
    }
    float* uruf;  cudaGetSymbolAddress((void**)&uruf, g_U);
    float* hbuf;  cudaGetSymbolAddress((void**)&hbuf, g_H);

    // smem: 128 + 3*128*36 + 3*32*136 floats = 128 + 13824 + 13056 = 27008 -> 108032 B
    const int SMEM = 27008 * 4;
    cudaFuncSetAttribute(k_gemm_mma<0>, cudaFuncAttributeMaxDynamicSharedMemorySize, SMEM);
    cudaFuncSetAttribute(k_gemm_mma<1>, cudaFuncAttributeMaxDynamicSharedMemorySize, SMEM);

    k_prep<<<(T_TOK * DIM / 4 + 255) / 256, 256>>>(u);           // idx 0
    k_router<<<T_TOK, 256>>>(u, cent, bias);                     // idx 1
    k_offscatter<<<1, 1024>>>(maxvio_ptr);                       // idx 2
    k_gemm_mma<0><<<dim3(16, HID / 128, NEXP), 256, SMEM>>>(uruf, W1, b1);  // idx 3
    k_gemm_mma<1><<<dim3(16, DIM / 128, NEXP), 256, SMEM>>>(hbuf, W2, b2);  // idx 4
    k_combine<<<T_TOK, 256>>>(b2, out);                          // idx 5
}